// round 1
// baseline (speedup 1.0000x reference)
#include <cuda_runtime.h>
#include <cuda_bf16.h>
#include <math.h>

// Problem constants
#define HIDDEN   2048
#define NHEADS   16
#define NKVHEADS 4
#define HEADDIM  128
#define BATCH    2
#define SEQ      2048
#define MROWS    (BATCH * SEQ)          // 4096
#define KVDIM    (NKVHEADS * HEADDIM)   // 512

// Scratch (allocation-free rule: __device__ globals)
__device__ float g_q[MROWS * HIDDEN];    // Q after proj (+RoPE): [b*S+s][h*128+d]
__device__ float g_k[MROWS * KVDIM];     // K after proj (+RoPE)
__device__ float g_v[MROWS * KVDIM];     // V
__device__ float g_attn[MROWS * HIDDEN]; // attention output before Wo

// ---------------------------------------------------------------------------
// Tiled fp32 GEMM with bias: C[M,N] = A[M,K] @ W[K,N] + bias[N]
// BM=128, BN=64, BK=16, TM=8, TN=4, 256 threads
// ---------------------------------------------------------------------------
__global__ __launch_bounds__(256) void sgemm_bias(
    const float* __restrict__ A, const float* __restrict__ W,
    const float* __restrict__ bias, float* __restrict__ C,
    int M, int N, int K)
{
    const int BM = 128, BN = 64, BK = 16, TM = 8, TN = 4;
    __shared__ float As[BK][BM + 4];   // transposed: As[k][m]
    __shared__ float Bs[BK][BN];

    const int tid = threadIdx.x;
    const int m0 = blockIdx.y * BM;
    const int n0 = blockIdx.x * BN;
    const int tr = tid / 16;   // 0..15  (row group)
    const int tc = tid % 16;   // 0..15  (col group)

    float acc[TM][TN];
#pragma unroll
    for (int i = 0; i < TM; i++)
#pragma unroll
        for (int j = 0; j < TN; j++) acc[i][j] = 0.f;

    for (int k0 = 0; k0 < K; k0 += BK) {
        // Load A tile: 128x16 = 512 float4, 2 per thread
#pragma unroll
        for (int l = 0; l < 2; l++) {
            int f = tid + l * 256;
            int m = f >> 2;
            int kk = (f & 3) * 4;
            float4 v = *(const float4*)(A + (size_t)(m0 + m) * K + k0 + kk);
            As[kk + 0][m] = v.x;
            As[kk + 1][m] = v.y;
            As[kk + 2][m] = v.z;
            As[kk + 3][m] = v.w;
        }
        // Load B tile: 16x64 = 256 float4, 1 per thread
        {
            int f = tid;
            int kk = f >> 4;
            int n = (f & 15) * 4;
            float4 v = *(const float4*)(W + (size_t)(k0 + kk) * N + n0 + n);
            *(float4*)&Bs[kk][n] = v;
        }
        __syncthreads();

#pragma unroll
        for (int kk = 0; kk < BK; kk++) {
            float a[TM], b[TN];
#pragma unroll
            for (int i = 0; i < TM; i++) a[i] = As[kk][tr * TM + i];
#pragma unroll
            for (int j = 0; j < TN; j++) b[j] = Bs[kk][tc * TN + j];
#pragma unroll
            for (int i = 0; i < TM; i++)
#pragma unroll
                for (int j = 0; j < TN; j++) acc[i][j] += a[i] * b[j];
        }
        __syncthreads();
    }

    // Epilogue + bias
    float4 bv = *(const float4*)(bias + n0 + tc * TN);
#pragma unroll
    for (int i = 0; i < TM; i++) {
        int row = m0 + tr * TM + i;
        float4 r;
        r.x = acc[i][0] + bv.x;
        r.y = acc[i][1] + bv.y;
        r.z = acc[i][2] + bv.z;
        r.w = acc[i][3] + bv.w;
        *(float4*)(C + (size_t)row * N + n0 + tc * TN) = r;
    }
}

// ---------------------------------------------------------------------------
// RoPE applied in-place to Q [4096, 16*128] and K [4096, 4*128]
// grid = 4096 blocks (one per (b,s)), 128 threads
// ---------------------------------------------------------------------------
__global__ __launch_bounds__(128) void rope_kernel(
    const int* __restrict__ pos_ids, float* __restrict__ Q, float* __restrict__ Kv)
{
    const int bs = blockIdx.x;
    const int t = threadIdx.x;
    __shared__ float cs[64], sn[64];

    if (t < 64) {
        double pos = (double)pos_ids[bs];
        // inv_freq = theta^(-t/64) = exp(-(t/64) * ln(1e6))
        double inv = exp(-((double)t / 64.0) * 13.815510557964274);
        double fr = pos * inv;
        cs[t] = (float)cos(fr);
        sn[t] = (float)sin(fr);
    }
    __syncthreads();

    float* q = Q + (size_t)bs * HIDDEN;
#pragma unroll
    for (int p = t; p < NHEADS * 64; p += 128) {
        int h = p >> 6;
        int d = p & 63;
        float* base = q + h * HEADDIM;
        float x0 = base[d];
        float x1 = base[d + 64];
        base[d]      = x0 * cs[d] - x1 * sn[d];
        base[d + 64] = x1 * cs[d] + x0 * sn[d];
    }
    float* k = Kv + (size_t)bs * KVDIM;
#pragma unroll
    for (int p = t; p < NKVHEADS * 64; p += 128) {
        int h = p >> 6;
        int d = p & 63;
        float* base = k + h * HEADDIM;
        float x0 = base[d];
        float x1 = base[d + 64];
        base[d]      = x0 * cs[d] - x1 * sn[d];
        base[d + 64] = x1 * cs[d] + x0 * sn[d];
    }
}

// ---------------------------------------------------------------------------
// Causal flash attention, GQA (4 q heads per kv head).
// grid = (S/128, NHEADS, B), 128 threads. Each thread owns one q row.
// Smem: Q tile 128x128 (pitch 132), K/V tiles 32x128 (pitch 132) => ~101 KB.
// ---------------------------------------------------------------------------
#define QPITCH 132
#define ATTN_SMEM_BYTES ((128 * QPITCH + 2 * 32 * QPITCH) * 4)

__global__ __launch_bounds__(128) void attn_kernel(
    const float* __restrict__ Qg, const float* __restrict__ Kg,
    const float* __restrict__ Vg, float* __restrict__ Og)
{
    extern __shared__ float smem[];
    float* Qs = smem;                     // 128 * 132
    float* Ks = Qs + 128 * QPITCH;        // 32 * 132
    float* Vs = Ks + 32 * QPITCH;         // 32 * 132

    const int t = threadIdx.x;
    const int qt = blockIdx.x;
    const int h = blockIdx.y;
    const int b = blockIdx.z;
    const int kvh = h >> 2;
    const int s = qt * 128 + t;
    const float scale = 0.08838834764831845f;  // 1/sqrt(128)

    // Cooperative load of Q tile (coalesced 512B rows)
    const float* qbase = Qg + ((size_t)(b * SEQ + qt * 128)) * HIDDEN + h * HEADDIM;
#pragma unroll
    for (int lq = 0; lq < 32; lq++) {
        int f = t + lq * 128;   // 0..4095 float4 slots
        int row = f >> 5;
        int d4 = f & 31;
        *(float4*)&Qs[row * QPITCH + d4 * 4] =
            *(const float4*)(qbase + (size_t)row * HIDDEN + d4 * 4);
    }

    float4 acc[32];
#pragma unroll
    for (int i = 0; i < 32; i++) acc[i] = make_float4(0.f, 0.f, 0.f, 0.f);
    float mrun = -1e30f, lrun = 0.f;

    const int nkv = (qt + 1) * 128;  // causal bound for this tile
    const float* kbase = Kg + (size_t)b * SEQ * KVDIM + kvh * HEADDIM;
    const float* vbase = Vg + (size_t)b * SEQ * KVDIM + kvh * HEADDIM;

    for (int kv0 = 0; kv0 < nkv; kv0 += 32) {
        __syncthreads();
        // Load K/V tiles: 32 rows x 32 float4 each
#pragma unroll
        for (int lq = 0; lq < 8; lq++) {
            int f = t + lq * 128;
            int row = f >> 5;
            int d4 = f & 31;
            *(float4*)&Ks[row * QPITCH + d4 * 4] =
                *(const float4*)(kbase + (size_t)(kv0 + row) * KVDIM + d4 * 4);
            *(float4*)&Vs[row * QPITCH + d4 * 4] =
                *(const float4*)(vbase + (size_t)(kv0 + row) * KVDIM + d4 * 4);
        }
        __syncthreads();

        // Scores: sc[j] = q_row . k_j, 4 k-rows at a time
        float sc[32];
#pragma unroll
        for (int j = 0; j < 32; j += 4) {
            float s0 = 0.f, s1 = 0.f, s2 = 0.f, s3 = 0.f;
#pragma unroll 8
            for (int d4 = 0; d4 < 32; d4++) {
                float4 q  = *(float4*)&Qs[t * QPITCH + d4 * 4];
                float4 k0 = *(float4*)&Ks[(j + 0) * QPITCH + d4 * 4];
                float4 k1 = *(float4*)&Ks[(j + 1) * QPITCH + d4 * 4];
                float4 k2 = *(float4*)&Ks[(j + 2) * QPITCH + d4 * 4];
                float4 k3 = *(float4*)&Ks[(j + 3) * QPITCH + d4 * 4];
                s0 += q.x * k0.x + q.y * k0.y + q.z * k0.z + q.w * k0.w;
                s1 += q.x * k1.x + q.y * k1.y + q.z * k1.z + q.w * k1.w;
                s2 += q.x * k2.x + q.y * k2.y + q.z * k2.z + q.w * k2.w;
                s3 += q.x * k3.x + q.y * k3.y + q.z * k3.z + q.w * k3.w;
            }
            sc[j] = s0; sc[j + 1] = s1; sc[j + 2] = s2; sc[j + 3] = s3;
        }

        // Causal mask + online softmax update
        float tmax = -1e30f;
#pragma unroll
        for (int j = 0; j < 32; j++) {
            sc[j] = (kv0 + j <= s) ? sc[j] * scale : -1e30f;
            tmax = fmaxf(tmax, sc[j]);
        }
        float mnew = fmaxf(mrun, tmax);
        float corr = __expf(mrun - mnew);
        mrun = mnew;
        lrun *= corr;
#pragma unroll
        for (int i = 0; i < 32; i++) {
            acc[i].x *= corr; acc[i].y *= corr; acc[i].z *= corr; acc[i].w *= corr;
        }
#pragma unroll
        for (int j = 0; j < 32; j++) {
            float p = __expf(sc[j] - mnew);
            sc[j] = p;
            lrun += p;
        }

        // acc += P @ V, 4 v-rows at a time (acc indexed with full unroll!)
#pragma unroll
        for (int j = 0; j < 32; j += 4) {
            float p0 = sc[j], p1 = sc[j + 1], p2 = sc[j + 2], p3 = sc[j + 3];
#pragma unroll
            for (int d4 = 0; d4 < 32; d4++) {
                float4 v0 = *(float4*)&Vs[(j + 0) * QPITCH + d4 * 4];
                float4 v1 = *(float4*)&Vs[(j + 1) * QPITCH + d4 * 4];
                float4 v2 = *(float4*)&Vs[(j + 2) * QPITCH + d4 * 4];
                float4 v3 = *(float4*)&Vs[(j + 3) * QPITCH + d4 * 4];
                acc[d4].x += p0 * v0.x + p1 * v1.x + p2 * v2.x + p3 * v3.x;
                acc[d4].y += p0 * v0.y + p1 * v1.y + p2 * v2.y + p3 * v3.y;
                acc[d4].z += p0 * v0.z + p1 * v1.z + p2 * v2.z + p3 * v3.z;
                acc[d4].w += p0 * v0.w + p1 * v1.w + p2 * v2.w + p3 * v3.w;
            }
        }
    }

    float invl = 1.f / lrun;
    float* ob = Og + ((size_t)(b * SEQ + s)) * HIDDEN + h * HEADDIM;
#pragma unroll
    for (int d4 = 0; d4 < 32; d4++) {
        float4 r;
        r.x = acc[d4].x * invl;
        r.y = acc[d4].y * invl;
        r.z = acc[d4].z * invl;
        r.w = acc[d4].w * invl;
        *(float4*)(ob + d4 * 4) = r;
    }
}

// ---------------------------------------------------------------------------
// Launch
// ---------------------------------------------------------------------------
extern "C" void kernel_launch(void* const* d_in, const int* in_sizes, int n_in,
                              void* d_out, int out_size)
{
    const float* hidden = (const float*)d_in[0];
    const int*   posids = (const int*)d_in[1];
    const float* Wq = (const float*)d_in[2];
    const float* bq = (const float*)d_in[3];
    const float* Wk = (const float*)d_in[4];
    const float* bk = (const float*)d_in[5];
    const float* Wv = (const float*)d_in[6];
    const float* bv = (const float*)d_in[7];
    const float* Wo = (const float*)d_in[8];
    const float* bo = (const float*)d_in[9];
    float* out = (float*)d_out;

    float *qp, *kp, *vp, *ap;
    cudaGetSymbolAddress((void**)&qp, g_q);
    cudaGetSymbolAddress((void**)&kp, g_k);
    cudaGetSymbolAddress((void**)&vp, g_v);
    cudaGetSymbolAddress((void**)&ap, g_attn);

    // QKV projections
    sgemm_bias<<<dim3(HIDDEN / 64, MROWS / 128), 256>>>(hidden, Wq, bq, qp, MROWS, HIDDEN, HIDDEN);
    sgemm_bias<<<dim3(KVDIM / 64, MROWS / 128), 256>>>(hidden, Wk, bk, kp, MROWS, KVDIM, HIDDEN);
    sgemm_bias<<<dim3(KVDIM / 64, MROWS / 128), 256>>>(hidden, Wv, bv, vp, MROWS, KVDIM, HIDDEN);

    // RoPE in-place on Q, K
    rope_kernel<<<MROWS, 128>>>(posids, qp, kp);

    // Flash attention (causal, GQA)
    cudaFuncSetAttribute(attn_kernel, cudaFuncAttributeMaxDynamicSharedMemorySize,
                         ATTN_SMEM_BYTES);
    attn_kernel<<<dim3(SEQ / 128, NHEADS, BATCH), 128, ATTN_SMEM_BYTES>>>(qp, kp, vp, ap);

    // Output projection into d_out
    sgemm_bias<<<dim3(HIDDEN / 64, MROWS / 128), 256>>>(ap, Wo, bo, out, MROWS, HIDDEN, HIDDEN);
}